// round 16
// baseline (speedup 1.0000x reference)
#include <cuda_runtime.h>
#include <cstdint>

// ---------------------------------------------------------------------------
// Heisenberg-collapsed circuit, Round 16: single kernel, plain-LDG eval.
//   <Z0> = e2x*e3x + (e0z*e1z) * (e2y*e3x + e2z)
// - 1024 CTAs x 256 threads, 2 samples/thread (geometry of the fastest
//   measured eval: R3 @ 5.86us kernel), front-batched LDG.128 at cycle 0.
// - Threads 0-5 compute the six weight-only K triples (affine form, short
//   chain ~400cyc) into smem; the single __syncthreads overlaps each
//   thread's own ~600cyc DRAM load latency, so the K prologue is ~free.
// - No TMA / mbarrier: the single-producer TMA issue + mbarrier sequence
//   measured ~0.7us slower than parallel per-thread LDGs at this geometry.
// ---------------------------------------------------------------------------

struct Cpx { float r, i; };
__device__ __forceinline__ Cpx cmul(Cpx a, Cpx b) { return {a.r*b.r - a.i*b.i, a.r*b.i + a.i*b.r}; }
__device__ __forceinline__ Cpx cconj(Cpx a)       { return {a.r, -a.i}; }
__device__ __forceinline__ Cpx cadd(Cpx a, Cpx b) { return {a.r + b.r, a.i + b.i}; }
__device__ __forceinline__ Cpx csub(Cpx a, Cpx b) { return {a.r - b.r, a.i - b.i}; }
__device__ __forceinline__ Cpx cmuli(Cpx a)       { return {-a.i, a.r}; }   // i*a

__device__ __forceinline__ void rot_mat(const float* __restrict__ w, Cpx R[4]) {
    float phi = w[0], th = w[1], om = w[2];
    float c, s, epi_n, epr, emi, emr;
    __sincosf(0.5f * th, &s, &c);
    __sincosf(0.5f * (phi + om), &epi_n, &epr);   // ep = (epr, -epi_n)
    __sincosf(0.5f * (phi - om), &emi, &emr);     // em = (emr, +emi)
    R[0] = {  epr * c, -epi_n * c };
    R[1] = { -emr * s, -emi   * s };
    R[2] = {  emr * s, -emi   * s };  // conj(em)*s
    R[3] = {  epr * c,  epi_n * c };  // conj(ep)*c
}

// e = K0 + K1*cos(x) + K2*sin(x) for <v|R^dag P R|v>, v = (cos x/2, -i sin x/2).
__device__ __forceinline__ void exp_coeffs(const Cpx R[4], int P, float scale, float* K) {
    float N00, N11;
    Cpx N01;
    if (P == 2) {            // Z
        N00 = (R[0].r*R[0].r + R[0].i*R[0].i) - (R[2].r*R[2].r + R[2].i*R[2].i);
        N01 = csub(cmul(cconj(R[0]), R[1]), cmul(cconj(R[2]), R[3]));
        N11 = (R[1].r*R[1].r + R[1].i*R[1].i) - (R[3].r*R[3].r + R[3].i*R[3].i);
    } else if (P == 0) {     // X
        Cpx z02 = cmul(cconj(R[0]), R[2]);
        Cpx z13 = cmul(cconj(R[1]), R[3]);
        N00 = 2.0f * z02.r;
        N01 = cadd(cmul(cconj(R[0]), R[3]), cmul(cconj(R[2]), R[1]));
        N11 = 2.0f * z13.r;
    } else {                 // Y
        Cpx z02 = cmul(cconj(R[0]), R[2]);
        Cpx z13 = cmul(cconj(R[1]), R[3]);
        N00 = 2.0f * z02.i;
        Cpx t1 = cmuli(cmul(cconj(R[0]), R[3]));
        Cpx t2 = cmuli(cmul(cconj(R[2]), R[1]));
        N01 = csub(t2, t1);
        N11 = 2.0f * z13.i;
    }
    K[0] = 0.5f * (N00 + N11) * scale;
    K[1] = 0.5f * (N00 - N11) * scale;
    K[2] = N01.i * scale;
}

__device__ __forceinline__ float eval_sample(float4 xv, const float* __restrict__ k) {
    float c0, s0, c1, s1, c2, s2, c3, s3;
    __sincosf(xv.x, &s0, &c0);
    __sincosf(xv.y, &s1, &c1);
    __sincosf(xv.z, &s2, &c2);
    __sincosf(xv.w, &s3, &c3);
    float e0z = fmaf(k[1],  c0, fmaf(k[2],  s0, k[0]));
    float e1z = fmaf(k[4],  c1, fmaf(k[5],  s1, k[3]));
    float e2x = fmaf(k[7],  c2, fmaf(k[8],  s2, k[6]));
    float e2y = fmaf(k[10], c2, fmaf(k[11], s2, k[9]));
    float e2z = fmaf(k[13], c2, fmaf(k[14], s2, k[12]));
    float e3x = fmaf(k[16], c3, fmaf(k[17], s3, k[15]));
    float t01 = e0z * e1z;
    return fmaf(e3x, fmaf(t01, e2y, e2x), t01 * e2z);
}

__global__ __launch_bounds__(256, 8)
void quantum_fused_ldg(const float4* __restrict__ x,
                       const float*  __restrict__ w,
                       float2* __restrict__ out, int Mpairs) {
    __shared__ __align__(16) float Ksh[20];

    int t = blockIdx.x * blockDim.x + threadIdx.x;
    bool valid = (t < Mpairs);

    // (1) Front-batch the two DRAM loads at cycle 0 (all threads, parallel).
    float4 xv0, xv1;
    if (valid) {
        const float4* p = x + 2 * (size_t)t;
        xv0 = __ldg(p + 0);
        xv1 = __ldg(p + 1);
    }

    // (2) Threads 0-5: six K triples in parallel, under the load latency.
    // map: 0->(w0,Z) 1->(w1,Z) 2->(w2,X*a) 3->(w2,Y*b) 4->(w2,Z*g) 5->(w3,X)
    if (threadIdx.x < 6) {
        int tt = threadIdx.x;
        int wire = (tt == 0) ? 0 : (tt == 1) ? 1 : (tt == 5) ? 3 : 2;
        int P    = (tt <= 1) ? 2 : (tt == 2) ? 0 : (tt == 3) ? 1 : (tt == 4) ? 2 : 0;

        float scale = 1.0f;
        if (tt >= 2 && tt <= 4) {
            // alpha/beta/gamma from layer-1 wire-2 Rot: M = R^dag Z R
            Cpx R1[4];
            rot_mat(w + (1 * 4 + 2) * 3, R1);
            float M00 = (R1[0].r*R1[0].r + R1[0].i*R1[0].i)
                      - (R1[2].r*R1[2].r + R1[2].i*R1[2].i);
            Cpx M01 = csub(cmul(cconj(R1[0]), R1[1]), cmul(cconj(R1[2]), R1[3]));
            scale = (tt == 2) ? M01.r : (tt == 3) ? -M01.i : M00;
        }

        Cpx R[4];
        rot_mat(w + wire * 3, R);
        float K[3];
        exp_coeffs(R, P, scale, K);
        Ksh[tt * 3 + 0] = K[0];
        Ksh[tt * 3 + 1] = K[1];
        Ksh[tt * 3 + 2] = K[2];
        if (tt == 0) { Ksh[18] = 0.0f; Ksh[19] = 0.0f; }
    }

    // (3) Barrier: non-K threads arrive immediately and its wait overlaps
    // their own in-flight DRAM loads.
    __syncthreads();

    if (!valid) return;

    float k[20];
    const float4* kp = (const float4*)Ksh;
    float4 ka = kp[0], kb = kp[1], kc = kp[2], kd = kp[3], ke = kp[4];
    k[0]=ka.x; k[1]=ka.y; k[2]=ka.z; k[3]=ka.w;
    k[4]=kb.x; k[5]=kb.y; k[6]=kb.z; k[7]=kb.w;
    k[8]=kc.x; k[9]=kc.y; k[10]=kc.z; k[11]=kc.w;
    k[12]=kd.x; k[13]=kd.y; k[14]=kd.z; k[15]=kd.w;
    k[16]=ke.x; k[17]=ke.y; k[18]=ke.z; k[19]=ke.w;

    float2 r;
    r.x = eval_sample(xv0, k);
    r.y = eval_sample(xv1, k);
    out[t] = r;
}

extern "C" void kernel_launch(void* const* d_in, const int* in_sizes, int n_in,
                              void* d_out, int out_size) {
    const float* x = (const float*)d_in[0];        // (64, 8192, 4) fp32
    const float* weights = (const float*)d_in[1];  // (2, 4, 3) fp32
    float2* out = (float2*)d_out;                  // (64, 8192, 1) fp32

    int M = in_sizes[0] / 4;                       // 524288 samples
    int Mpairs = M / 2;                            // 262144 -> 1024 CTAs exact

    quantum_fused_ldg<<<(Mpairs + 255) / 256, 256>>>(
        (const float4*)x, weights, out, Mpairs);
}